// round 15
// baseline (speedup 1.0000x reference)
#include <cuda_runtime.h>
#include <cuda_bf16.h>
#include <cstdint>

#define LOG2E 1.4426950408889634f
#define NPTS 4096
#define NT 1024                       // 32x32 tiles of 128x128

// mma.sync m16n8k16 bf16 (row.col), f32 accum.
#define MMA16816(c, a, b0v, b1v)                                               \
    asm("mma.sync.aligned.m16n8k16.row.col.f32.bf16.bf16.f32 "                 \
        "{%0,%1,%2,%3}, {%4,%5,%6,%7}, {%8,%9}, {%0,%1,%2,%3};"                \
        : "+f"((c)[0]), "+f"((c)[1]), "+f"((c)[2]), "+f"((c)[3])               \
        : "r"((a)[0]), "r"((a)[1]), "r"((a)[2]), "r"((a)[3]),                  \
          "r"(b0v), "r"(b1v))

#define EX2(v) asm("ex2.approx.ftz.f32 %0, %0;" : "+f"(v))

// smem: A parity-buffered by i-tile, B double-buffered per tile (96B rows)
#define A_OFF(p)  ((p) * 12288)
#define B_OFF(b)  (24576 + (b) * 12288)
#define CS_OFF(p) (49152 + (p) * 512)
#define DS_OFF(b) (50176 + (b) * 512)
#define PRMOFF    51200
#define SMEM_REQ  51328

extern __shared__ char smem[];

__device__ __forceinline__ uint32_t pack_bf2(__nv_bfloat16 a, __nv_bfloat16 b) {
    __nv_bfloat162 t(a, b);
    return *reinterpret_cast<uint32_t*>(&t);
}

// Persistent-CTA RBF, contiguous-chunk tiles: cov = exp2(S + c_i + d_j),
// S = 3-term bf16 split GEMM (K=48: A=[uh|ul|uh], B=[vh|vh|vl]).
// A-side (x rows): converted once per i-tile, af/ci stay in registers
// across j-tiles. B-side converted per tile, permuted rows -> STG.128.
__global__ void __launch_bounds__(256, 2) rbf_mma_p(
    const float* __restrict__ x,         // [4096,16]
    const float* __restrict__ xx,        // [4096,16]
    const float* __restrict__ scale_ff,  // [16]
    const float* __restrict__ var_ff,    // scalar
    float* __restrict__ out)             // [4096,4096]
{
    const int tid  = threadIdx.x;
    const int wid  = tid >> 5;
    const int lane = tid & 31;
    float* SINV = (float*)(smem + PRMOFF);   // [16] inv-scale, [16]=log2(var)

    if (tid >= 32 && tid < 48) {
        SINV[tid - 32] = 1.0f / log1pf(__expf(scale_ff[tid - 32]));
    } else if (tid == 48) {
        SINV[16] = log2f(log1pf(__expf(var_ff[0])));
    }

    const bool is_x = (tid < 128);
    const int rowid = tid & 127;
    const int G = gridDim.x;
    const int tstart = (blockIdx.x * NT) / G;
    const int tend   = ((blockIdx.x + 1) * NT) / G;

    int t = tstart;
    float4 ra, rb, rc, rd;
    if (t < tend) {
        const float4* rowp = is_x
            ? (const float4*)(x  + (size_t)((t >> 5) * 128 + rowid) * 16)
            : (const float4*)(xx + (size_t)((t & 31) * 128 + rowid) * 16);
        ra = rowp[0]; rb = rowp[1]; rc = rowp[2]; rd = rowp[3];
    }
    __syncthreads();   // SINV ready

    const int qrow = lane >> 2;
    const int qcol = lane & 3;
    const int wr = (wid & 3) * 32;
    const int wc = (wid >> 2) * 64;

    uint32_t af[3][2][4];   // persistent across j-tiles of an i-tile
    float ci[4];
    int cur_i = -1;
    int bbuf = 0;

    while (t < tend) {
        const int it = t >> 5, jt = t & 31;
        const bool new_i = (it != cur_i);
        const int ip = it & 1;
        const int bi0 = it * 128, bj0 = jt * 128;

        // ---- convert: A only on i-change (threads 0-127), B every tile ----
        {
            float vals[16] = {ra.x, ra.y, ra.z, ra.w, rb.x, rb.y, rb.z, rb.w,
                              rc.x, rc.y, rc.z, rc.w, rd.x, rd.y, rd.z, rd.w};
            if ((is_x && new_i) || !is_x) {
                uint32_t hp[8], lp[8];
                float s2 = 0.0f;
#pragma unroll
                for (int d = 0; d < 16; d += 2) {
                    float u0 = vals[d] * SINV[d];
                    float u1 = vals[d + 1] * SINV[d + 1];
                    s2 = fmaf(u0, u0, fmaf(u1, u1, s2));
                    float w0 = is_x ? u0 : (LOG2E * u0);
                    float w1 = is_x ? u1 : (LOG2E * u1);
                    __nv_bfloat16 h0 = __float2bfloat16_rn(w0);
                    __nv_bfloat16 h1 = __float2bfloat16_rn(w1);
                    __nv_bfloat16 l0 = __float2bfloat16_rn(w0 - __bfloat162float(h0));
                    __nv_bfloat16 l1 = __float2bfloat16_rn(w1 - __bfloat162float(h1));
                    hp[d >> 1] = pack_bf2(h0, h1);
                    lp[d >> 1] = pack_bf2(l0, l1);
                }
                // pair-interleaved groups: phys {w0,w4,w1,w5},{w2,w6,w3,w7}
                uint4 H0 = make_uint4(hp[0], hp[4], hp[1], hp[5]);
                uint4 H1 = make_uint4(hp[2], hp[6], hp[3], hp[7]);
                uint4 L0 = make_uint4(lp[0], lp[4], lp[1], lp[5]);
                uint4 L1 = make_uint4(lp[2], lp[6], lp[3], lp[7]);
                if (is_x) {
                    uint4* dst = (uint4*)(smem + A_OFF(ip) + rowid * 96);
                    dst[0] = H0; dst[1] = H1;   // k0: uh
                    dst[2] = L0; dst[3] = L1;   // k1: ul
                    dst[4] = H0; dst[5] = H1;   // k2: uh
                    ((float*)(smem + CS_OFF(ip)))[rowid] = -0.5f * LOG2E * s2;
                } else {
                    // permuted slot: j64 bits (k,qc,m,e) -> slot (k,m,qc,e)
                    const int j64 = rowid & 63;
                    const int slot = (j64 & 0x30) | ((j64 & 2) << 2) |
                                     ((j64 & 0xC) >> 1) | (j64 & 1);
                    const int brow = (rowid & 64) + slot;
                    uint4* dst = (uint4*)(smem + B_OFF(bbuf) + brow * 96);
                    dst[0] = H0; dst[1] = H1;   // k0: vh
                    dst[2] = H0; dst[3] = H1;   // k1: vh
                    dst[4] = L0; dst[5] = L1;   // k2: vl
                    ((float*)(smem + DS_OFF(bbuf)))[rowid] =
                        -0.5f * LOG2E * s2 + SINV[16];
                }
            }
        }

        // ---- prefetch rows for tile t+1 (B always; x only on i-change) ----
        const int tn = t + 1;
        if (tn < tend) {
            if (is_x) {
                if ((tn >> 5) != it) {
                    const float4* rowp = (const float4*)
                        (x + (size_t)((tn >> 5) * 128 + rowid) * 16);
                    ra = rowp[0]; rb = rowp[1]; rc = rowp[2]; rd = rowp[3];
                }
            } else {
                const float4* rowp = (const float4*)
                    (xx + (size_t)((tn & 31) * 128 + rowid) * 16);
                ra = rowp[0]; rb = rowp[1]; rc = rowp[2]; rd = rowp[3];
            }
        }
        __syncthreads();   // smem tiles ready

        // ---- refresh A fragments only when i changed ----
        if (new_i) {
            const char* Ab = smem + A_OFF(ip) + (wr + qrow) * 96 + qcol * 8;
#pragma unroll
            for (int ks = 0; ks < 3; ks++) {
#pragma unroll
                for (int mt = 0; mt < 2; mt++) {
                    uint2 p = *(const uint2*)(Ab + mt * 1536 + ks * 32);
                    uint2 q = *(const uint2*)(Ab + mt * 1536 + 768 + ks * 32);
                    af[ks][mt][0] = p.x;
                    af[ks][mt][1] = q.x;
                    af[ks][mt][2] = p.y;
                    af[ks][mt][3] = q.y;
                }
            }
            const float* CSb = (const float*)(smem + CS_OFF(ip)) + wr + qrow;
            ci[0] = CSb[0];  ci[1] = CSb[8];
            ci[2] = CSb[16]; ci[3] = CSb[24];
            cur_i = it;
        }

        // ---- compute tile (R13 body): 12 MMA -> 16 EX2 -> 4 STG per group ----
        const char* Bb = smem + B_OFF(bbuf);
        const float* DJ = (const float*)(smem + DS_OFF(bbuf));
#pragma unroll
        for (int k = 0; k < 4; k++) {
            float4 dj = *(const float4*)(DJ + wc + 16 * k + 4 * qcol);
            float a0[2][4], a1[2][4];   // nt=2k, nt=2k+1
#pragma unroll
            for (int mt = 0; mt < 2; mt++) {
                a0[mt][0] = ci[2 * mt] + dj.x;
                a0[mt][1] = ci[2 * mt] + dj.y;
                a0[mt][2] = ci[2 * mt + 1] + dj.x;
                a0[mt][3] = ci[2 * mt + 1] + dj.y;
                a1[mt][0] = ci[2 * mt] + dj.z;
                a1[mt][1] = ci[2 * mt] + dj.w;
                a1[mt][2] = ci[2 * mt + 1] + dj.z;
                a1[mt][3] = ci[2 * mt + 1] + dj.w;
            }
            const int jr0 = wc + 16 * k + qrow;
            const int jr1 = jr0 + 8;
#pragma unroll
            for (int ks = 0; ks < 3; ks++) {
                uint2 b0 = *(const uint2*)(Bb + jr0 * 96 + ks * 32 + qcol * 8);
                uint2 b1 = *(const uint2*)(Bb + jr1 * 96 + ks * 32 + qcol * 8);
                MMA16816(a0[0], af[ks][0], b0.x, b0.y);
                MMA16816(a0[1], af[ks][1], b0.x, b0.y);
                MMA16816(a1[0], af[ks][0], b1.x, b1.y);
                MMA16816(a1[1], af[ks][1], b1.x, b1.y);
            }
            const int col = bj0 + wc + 16 * k + 4 * qcol;
#pragma unroll
            for (int mt = 0; mt < 2; mt++) {
                float f0 = a0[mt][0], f1 = a0[mt][1];
                float f2 = a1[mt][0], f3 = a1[mt][1];
                float g0 = a0[mt][2], g1 = a0[mt][3];
                float g2 = a1[mt][2], g3 = a1[mt][3];
                EX2(f0); EX2(f1); EX2(f2); EX2(f3);
                EX2(g0); EX2(g1); EX2(g2); EX2(g3);
                const int r0g = bi0 + wr + mt * 16 + qrow;
                *(float4*)&out[(size_t)r0g * NPTS + col] =
                    make_float4(f0, f1, f2, f3);
                *(float4*)&out[(size_t)(r0g + 8) * NPTS + col] =
                    make_float4(g0, g1, g2, g3);
            }
        }

        t = tn;
        bbuf ^= 1;
    }
}

extern "C" void kernel_launch(void* const* d_in, const int* in_sizes, int n_in,
                              void* d_out, int out_size) {
    const float* x        = (const float*)d_in[0];
    const float* xx       = (const float*)d_in[1];
    const float* scale_ff = (const float*)d_in[2];
    const float* var_ff   = (const float*)d_in[3];
    float* out = (float*)d_out;

    int sms = 148;
    cudaDeviceGetAttribute(&sms, cudaDevAttrMultiProcessorCount, 0);
    int grid = 2 * sms;
    if (grid > NT) grid = NT;

    cudaFuncSetAttribute(rbf_mma_p, cudaFuncAttributeMaxDynamicSharedMemorySize,
                         SMEM_REQ);
    rbf_mma_p<<<grid, 256, SMEM_REQ>>>(x, xx, scale_ff, var_ff, out);
}